// round 15
// baseline (speedup 1.0000x reference)
#include <cuda_runtime.h>
#include <cuda_bf16.h>
#include <cstdint>

// Fixed problem shape: B=8, S=4096, D=512, E=16
#define N_TOK 32768
#define DIM   512
#define NEXP  16
#define CAP   2457   // int(1.2 * 32768 / 16)
#define NBLK  1024   // router blocks (32 tokens each)

// ---------------- scratch (device globals; no allocation allowed) ----------
__device__ __align__(16) __nv_bfloat16 g_xh[N_TOK * DIM];
__device__ __align__(16) __nv_bfloat16 g_xl[N_TOK * DIM];
__device__ __align__(16) __nv_bfloat16 g_wh[NEXP * DIM * DIM];
__device__ __align__(16) __nv_bfloat16 g_wl[NEXP * DIM * DIM];
__device__ int   g_routes[N_TOK];
__device__ float g_probs[N_TOK];
__device__ int   g_blkcnt[NEXP * NBLK];
__device__ int   g_blkoff[NEXP * NBLK];
__device__ int   g_idx[NEXP * CAP];
__device__ int   g_count[NEXP];
__device__ int   g_scanflag;

// ---------------- PTX helpers ----------------------------------------------
__device__ __forceinline__ uint32_t smem_u32(const void* p) {
    uint32_t a;
    asm("{ .reg .u64 t; cvta.to.shared.u64 t, %1; cvt.u32.u64 %0, t; }"
        : "=r"(a) : "l"(p));
    return a;
}
__device__ __forceinline__ uint32_t swz(uint32_t b) {   // 64B-row swizzle
    return b ^ ((b >> 3) & 0x30);
}
__device__ __forceinline__ void cp16(uint32_t dst, const void* src) {
    asm volatile("cp.async.cg.shared.global [%0], [%1], 16;\n"
                 :: "r"(dst), "l"(src));
}
#define CP_COMMIT() asm volatile("cp.async.commit_group;\n" ::: "memory")
#define CP_WAIT1()  asm volatile("cp.async.wait_group 1;\n" ::: "memory")

__device__ __forceinline__ void ldsm4(uint32_t* r, uint32_t a) {
    asm volatile("ldmatrix.sync.aligned.m8n8.x4.shared.b16 {%0,%1,%2,%3}, [%4];\n"
                 : "=r"(r[0]), "=r"(r[1]), "=r"(r[2]), "=r"(r[3]) : "r"(a));
}
__device__ __forceinline__ void mma16816(float* d, const uint32_t* a,
                                         const uint32_t* b) {
    asm volatile(
        "mma.sync.aligned.m16n8k16.row.col.f32.bf16.bf16.f32 "
        "{%0,%1,%2,%3}, {%4,%5,%6,%7}, {%8,%9}, {%0,%1,%2,%3};\n"
        : "+f"(d[0]), "+f"(d[1]), "+f"(d[2]), "+f"(d[3])
        : "r"(a[0]), "r"(a[1]), "r"(a[2]), "r"(a[3]), "r"(b[0]), "r"(b[1]));
}

// split one float4 into hi/lo bf16x4 packed as uint2
__device__ __forceinline__ void split4(float4 v, uint2& hv, uint2& lv) {
    float hx = __bfloat162float(__float2bfloat16_rn(v.x));
    float hy = __bfloat162float(__float2bfloat16_rn(v.y));
    float hz = __bfloat162float(__float2bfloat16_rn(v.z));
    float hw = __bfloat162float(__float2bfloat16_rn(v.w));
    __nv_bfloat162 h0 = __floats2bfloat162_rn(hx, hy);
    __nv_bfloat162 h1 = __floats2bfloat162_rn(hz, hw);
    __nv_bfloat162 l0 = __floats2bfloat162_rn(v.x - hx, v.y - hy);
    __nv_bfloat162 l1 = __floats2bfloat162_rn(v.z - hz, v.w - hw);
    hv = make_uint2(*(uint32_t*)&h0, *(uint32_t*)&h1);
    lv = make_uint2(*(uint32_t*)&l0, *(uint32_t*)&l1);
}

// ---------------- 1) fused router + x-split + W-split + block counts --------
// Router: float4 loads, uint2 hi/lo stores (3 LSU ops vs 12 scalar), two
// passes of 8 experts; whole kernel reg-capped at 64 via launch_bounds(256,4).
#define RW_ROUTER_BLOCKS NBLK                               // 1024
#define RW_WCONV_BLOCKS  (NEXP * DIM * DIM / 4 / 256)       // 4096

__global__ void __launch_bounds__(256, 4)
rw_kernel(const float* __restrict__ x,
          const float* __restrict__ sw,
          const float* __restrict__ sb,
          const float* __restrict__ ew) {
    int tid = threadIdx.x;

    if (blockIdx.x >= RW_ROUTER_BLOCKS) {
        // ---- wconv part (streaming, float4 in / uint2 x2 out) ----
        size_t idx = (size_t)(blockIdx.x - RW_ROUTER_BLOCKS) * 256 + tid;
        float4 v = ((const float4*)ew)[idx];
        uint2 hv, lv;
        split4(v, hv, lv);
        *(uint2*)(g_wh + idx * 4) = hv;
        *(uint2*)(g_wl + idx * 4) = lv;
        return;
    }

    // ---- router part: 32 tokens/block, 4 tokens/warp, vectorized ----
    if (blockIdx.x == 0 && tid == 0) g_scanflag = 0;   // reset sf flag barrier
    __shared__ float s_w[NEXP][DIM];
    __shared__ float s_b[NEXP];
    __shared__ float s_log[32][NEXP];
    __shared__ int   s_routes[32];
    for (int i = tid; i < NEXP * DIM / 4; i += 256)
        ((float4*)&s_w[0][0])[i] = ((const float4*)sw)[i];
    if (tid < NEXP) s_b[tid] = sb[tid];
    __syncthreads();

    int warp = tid >> 5, lane = tid & 31;
    int t0 = blockIdx.x * 32 + warp * 4;

#pragma unroll 1
    for (int half = 0; half < 2; half++) {
        float acc[4][8];
#pragma unroll
        for (int tt = 0; tt < 4; tt++)
#pragma unroll
            for (int e = 0; e < 8; e++) acc[tt][e] = 0.f;

#pragma unroll
        for (int j = 0; j < 4; j++) {
            int f4 = j * 32 + lane;            // float4 index within row
            float4 xv[4];
#pragma unroll
            for (int tt = 0; tt < 4; tt++) {
                xv[tt] = ((const float4*)(x + (size_t)(t0 + tt) * DIM))[f4];
                if (half == 0) {
                    uint2 hv, lv;
                    split4(xv[tt], hv, lv);
                    *(uint2*)(g_xh + (size_t)(t0 + tt) * DIM + f4 * 4) = hv;
                    *(uint2*)(g_xl + (size_t)(t0 + tt) * DIM + f4 * 4) = lv;
                }
            }
#pragma unroll
            for (int e = 0; e < 8; e++) {
                float4 w = ((const float4*)&s_w[half * 8 + e][0])[f4];
#pragma unroll
                for (int tt = 0; tt < 4; tt++) {
                    acc[tt][e] = fmaf(xv[tt].x, w.x, acc[tt][e]);
                    acc[tt][e] = fmaf(xv[tt].y, w.y, acc[tt][e]);
                    acc[tt][e] = fmaf(xv[tt].z, w.z, acc[tt][e]);
                    acc[tt][e] = fmaf(xv[tt].w, w.w, acc[tt][e]);
                }
            }
        }
#pragma unroll
        for (int tt = 0; tt < 4; tt++)
#pragma unroll
            for (int e = 0; e < 8; e++)
#pragma unroll
                for (int off = 16; off > 0; off >>= 1)
                    acc[tt][e] += __shfl_xor_sync(0xffffffffu, acc[tt][e], off);
        if (lane == 0) {
#pragma unroll
            for (int tt = 0; tt < 4; tt++)
#pragma unroll
                for (int e = 0; e < 8; e++)
                    s_log[warp * 4 + tt][half * 8 + e] = acc[tt][e];
        }
    }
    __syncwarp();

    if (lane < 4) {
        int tt = lane;
        float lmax = -1e30f; int am = 0;
        float l[NEXP];
#pragma unroll
        for (int e = 0; e < NEXP; e++) {
            l[e] = s_log[warp * 4 + tt][e] + s_b[e];
            if (l[e] > lmax) { lmax = l[e]; am = e; }
        }
        float sum = 0.f;
#pragma unroll
        for (int e = 0; e < NEXP; e++) sum += expf(l[e] - lmax);
        g_routes[t0 + tt] = am;
        g_probs[t0 + tt]  = 1.f / sum;
        s_routes[warp * 4 + tt] = am;
    }
    __syncthreads();
    if (tid < NEXP) {
        int c = 0;
#pragma unroll
        for (int i = 0; i < 32; i++) c += (s_routes[i] == tid);
        g_blkcnt[tid * NBLK + blockIdx.x] = c;
    }
}

// ---------------- 2) merged scan + finalize ----------------------------------
__global__ void __launch_bounds__(256, 8)
sf_kernel(const float* __restrict__ x, float* __restrict__ out) {
    __shared__ int s_ws[8];
    __shared__ unsigned s_drop;
    int blk = blockIdx.x;
    int tid = threadIdx.x, lane = tid & 31, wid = tid >> 5;

    if (blk < NEXP) {
        int e = blk;
        int4 c = ((const int4*)(g_blkcnt + e * NBLK))[tid];
        int sum = c.x + c.y + c.z + c.w;
        int inc = sum;
#pragma unroll
        for (int off = 1; off < 32; off <<= 1) {
            int o = __shfl_up_sync(0xffffffffu, inc, off);
            if (lane >= off) inc += o;
        }
        if (lane == 31) s_ws[wid] = inc;
        __syncthreads();
        if (wid == 0 && lane < 8) {
            int v = s_ws[lane];
            int wi = v;
#pragma unroll
            for (int off = 1; off < 8; off <<= 1) {
                int o = __shfl_up_sync(0xffu, wi, off);
                if (lane >= off) wi += o;
            }
            s_ws[lane] = wi - v;
        }
        __syncthreads();
        int excl = s_ws[wid] + inc - sum;
        int4 o;
        o.x = excl; o.y = excl + c.x; o.z = o.y + c.y; o.w = o.z + c.z;
        ((int4*)(g_blkoff + e * NBLK))[tid] = o;
        if (tid == 255) {
            int tot = excl + sum;
            g_count[e] = tot < CAP ? tot : CAP;
        }
        __syncthreads();
        if (tid == 0) {
            __threadfence();
            atomicAdd(&g_scanflag, 1);
        }
    }

    if (tid == 0) {
        while (*(volatile int*)&g_scanflag < NEXP) { }
        s_drop = 0;
    }
    __syncthreads();
    __threadfence();

    if (tid < 32) {
        int t = blk * 32 + tid;
        int r = g_routes[t];
        unsigned mask = __match_any_sync(0xffffffffu, r);
        int rank = __popc(mask & ((1u << tid) - 1u));
        int pos = g_blkoff[r * NBLK + blk] + rank;
        bool keep = pos < CAP;
        if (keep) g_idx[r * CAP + pos] = t;
        unsigned dm = __ballot_sync(0xffffffffu, !keep);
        if (tid == 0) s_drop = dm;
    }
    __syncthreads();
    unsigned dm = s_drop;
    while (dm) {
        int d = __ffs(dm) - 1;
        dm &= dm - 1;
        int t = blk * 32 + d;
        float p = g_probs[t];
        if (tid < 128) {
            float4 v = ((const float4*)(x + (size_t)t * DIM))[tid];
            v.x *= p; v.y *= p; v.z *= p; v.w *= p;
            ((float4*)(out + (size_t)t * DIM))[tid] = v;
        }
    }
}

// ---------------- 3) mma.sync grouped gather-GEMM (R10, FROZEN) -------------
#define BM 128
#define BN 128
#define BK 32
#define NSTG 3
#define OFF_AH 0
#define OFF_AL (8 * 1024)
#define OFF_BH (16 * 1024)
#define OFF_BL (24 * 1024)
#define STG_BYTES (32 * 1024)
#define SMEM_DYN  (NSTG * STG_BYTES + 1024)

__global__ void __launch_bounds__(256, 2)
moe_mma_kernel(const float* __restrict__ eb, float* __restrict__ out) {
    extern __shared__ char dynsmem[];
    __shared__ int   s_idx[BM];
    __shared__ float s_prob[BM];
    __shared__ float s_bias[BN];

    int e = blockIdx.z;
    int cnt = g_count[e];
    int m0 = blockIdx.x * BM;
    if (m0 >= cnt) return;
    int n0 = blockIdx.y * BN;
    int tid = threadIdx.x, wid = tid >> 5, lane = tid & 31;
    int wm = wid >> 2, wn = wid & 3;

    char* sbase = dynsmem + ((1024u - (smem_u32(dynsmem) & 1023u)) & 1023u);
    uint32_t u0 = smem_u32(sbase);

    if (tid < BM) {
        int m = m0 + tid;
        int t = g_idx[e * CAP + (m < cnt ? m : cnt - 1)];
        s_idx[tid] = t;
        s_prob[tid] = g_probs[t];
    }
    if (tid < BN) s_bias[tid] = eb[e * DIM + n0 + tid];
    __syncthreads();

    const __nv_bfloat16 *srcAh[2], *srcAl[2], *srcBh[2], *srcBl[2];
    uint32_t a_dst[2], b_dst[2];
#pragma unroll
    for (int i = 0; i < 2; i++) {
        int idx = tid + 256 * i;
        int row = idx >> 2, ch = idx & 3;
        size_t ao = (size_t)s_idx[row] * DIM + ch * 8;
        srcAh[i] = g_xh + ao;
        srcAl[i] = g_xl + ao;
        size_t bo = (size_t)(e * DIM + n0 + row) * DIM + ch * 8;
        srcBh[i] = g_wh + bo;
        srcBl[i] = g_wl + bo;
        a_dst[i] = swz((uint32_t)(row * 64 + ch * 16));
        b_dst[i] = a_dst[i];
    }

    const int KT = DIM / BK;   // 16
#pragma unroll
    for (int pre = 0; pre < 2; pre++) {
        uint32_t sb = u0 + pre * STG_BYTES;
        int kb = pre * BK;
#pragma unroll
        for (int i = 0; i < 2; i++) {
            cp16(sb + OFF_AH + a_dst[i], srcAh[i] + kb);
            cp16(sb + OFF_AL + a_dst[i], srcAl[i] + kb);
            cp16(sb + OFF_BH + b_dst[i], srcBh[i] + kb);
            cp16(sb + OFF_BL + b_dst[i], srcBl[i] + kb);
        }
        CP_COMMIT();
    }

    float acc[4][4][4];
#pragma unroll
    for (int mi = 0; mi < 4; mi++)
#pragma unroll
        for (int nj = 0; nj < 4; nj++)
#pragma unroll
            for (int k = 0; k < 4; k++) acc[mi][nj][k] = 0.f;

#pragma unroll 1
    for (int kt = 0; kt < KT; kt++) {
        CP_WAIT1();
        __syncthreads();
        if (kt + 2 < KT) {
            uint32_t sb = u0 + ((kt + 2) % NSTG) * STG_BYTES;
            int kb = (kt + 2) * BK;
#pragma unroll
            for (int i = 0; i < 2; i++) {
                cp16(sb + OFF_AH + a_dst[i], srcAh[i] + kb);
                cp16(sb + OFF_AL + a_dst[i], srcAl[i] + kb);
                cp16(sb + OFF_BH + b_dst[i], srcBh[i] + kb);
                cp16(sb + OFF_BL + b_dst[i], srcBl[i] + kb);
            }
        }
        CP_COMMIT();

        uint32_t sb = u0 + (kt % NSTG) * STG_BYTES;
#pragma unroll
        for (int ks = 0; ks < 2; ks++) {
            uint32_t ah[4][4], al[4][4], bh[4][2], bl[4][2];
            uint32_t a_addr[4], b_addr[2];
#pragma unroll
            for (int mi = 0; mi < 4; mi++) {
                uint32_t off = (uint32_t)((wm * 64 + mi * 16 + (lane & 15)) * 64 +
                                          ks * 32 + (lane >> 4) * 16);
                a_addr[mi] = sb + swz(off);
            }
#pragma unroll
            for (int nj2 = 0; nj2 < 2; nj2++) {
                uint32_t off = (uint32_t)((wn * 32 + nj2 * 16 +
                                           ((lane >> 4) & 1) * 8 + (lane & 7)) * 64 +
                                          ks * 32 + ((lane >> 3) & 1) * 16);
                b_addr[nj2] = sb + swz(off);
            }

            // wave 1: B-hi + A-hi, then ah*bh
#pragma unroll
            for (int nj2 = 0; nj2 < 2; nj2++) {
                uint32_t r[4];
                ldsm4(r, b_addr[nj2] + OFF_BH);
                bh[nj2 * 2][0] = r[0]; bh[nj2 * 2][1] = r[1];
                bh[nj2 * 2 + 1][0] = r[2]; bh[nj2 * 2 + 1][1] = r[3];
            }
#pragma unroll
            for (int mi = 0; mi < 4; mi++)
                ldsm4(ah[mi], a_addr[mi] + OFF_AH);
#pragma unroll
            for (int mi = 0; mi < 4; mi++)
#pragma unroll
                for (int nj = 0; nj < 4; nj++)
                    mma16816(acc[mi][nj], ah[mi], bh[nj]);

            // wave 2: B-lo, then ah*bl
#pragma unroll
            for (int nj2 = 0; nj2 < 2; nj2++) {
                uint32_t r[4];
                ldsm4(r, b_addr[nj2] + OFF_BL);
                bl[nj2 * 2][0] = r[0]; bl[nj2 * 2][1] = r[1];
                bl[nj2 * 2 + 1][0] = r[2]; bl[nj2 * 2 + 1][1] = r[3];
            }
#pragma unroll
            for (int mi = 0; mi < 4; mi++)
#pragma unroll
                for (int nj = 0; nj < 4; nj++)
                    mma16816(acc[mi][nj], ah[mi], bl[nj]);

            // wave 3: A-lo, then al*bh
#pragma unroll
            for (int mi = 0; mi < 4; mi++)
                ldsm4(al[mi], a_addr[mi] + OFF_AL);
#pragma unroll
            for (int mi = 0; mi < 4; mi++)
#pragma unroll
                for (int nj = 0; nj < 4; nj++)
                    mma16816(acc[mi][nj], al[mi], bh[nj]);
        }
    }

    // epilogue: +bias, *prob, scatter rows to out
#pragma unroll
    for (int mi = 0; mi < 4; mi++) {
        int r0 = wm * 64 + mi * 16 + (lane >> 2);
        int r1 = r0 + 8;
        bool ok0 = (m0 + r0) < cnt;
        bool ok1 = (m0 + r1) < cnt;
        float p0 = s_prob[r0], p1 = s_prob[r1];
        float* o0 = out + (size_t)s_idx[r0] * DIM + n0;
        float* o1 = out + (size_t)s_idx[r1] * DIM + n0;
#pragma unroll
        for (int nj = 0; nj < 4; nj++) {
            int col = wn * 32 + nj * 8 + 2 * (lane & 3);
            float b0 = s_bias[col], b1 = s_bias[col + 1];
            if (ok0) {
                float2 v = make_float2((acc[mi][nj][0] + b0) * p0,
                                       (acc[mi][nj][1] + b1) * p0);
                *(float2*)(o0 + col) = v;
            }
            if (ok1) {
                float2 v = make_float2((acc[mi][nj][2] + b0) * p1,
                                       (acc[mi][nj][3] + b1) * p1);
                *(float2*)(o1 + col) = v;
            }
        }
    }
}

// ---------------------------------------------------------------------------
extern "C" void kernel_launch(void* const* d_in, const int* in_sizes, int n_in,
                              void* d_out, int out_size) {
    const float* x   = (const float*)d_in[0];   // [N, D]
    const float* sw  = (const float*)d_in[1];   // [E, D]
    const float* sb  = (const float*)d_in[2];   // [E]
    const float* ew  = (const float*)d_in[3];   // [E, D, D]
    const float* ebv = (const float*)d_in[4];   // [E, D]
    float* out = (float*)d_out;

    cudaFuncSetAttribute(moe_mma_kernel,
                         cudaFuncAttributeMaxDynamicSharedMemorySize, SMEM_DYN);

    rw_kernel<<<RW_ROUTER_BLOCKS + RW_WCONV_BLOCKS, 256>>>(x, sw, sb, ew);
    sf_kernel<<<NBLK, 256>>>(x, out);

    dim3 grid((CAP + BM - 1) / BM, DIM / BN, NEXP);
    moe_mma_kernel<<<grid, 256, SMEM_DYN>>>(ebv, out);
}

// round 16
// speedup vs baseline: 1.0603x; 1.0603x over previous
#include <cuda_runtime.h>
#include <cuda_bf16.h>
#include <cstdint>

// Fixed problem shape: B=8, S=4096, D=512, E=16
#define N_TOK 32768
#define DIM   512
#define NEXP  16
#define CAP   2457   // int(1.2 * 32768 / 16)
#define NBLK  1024   // router blocks (32 tokens each)

// ---------------- scratch (device globals; no allocation allowed) ----------
__device__ __align__(16) __nv_bfloat16 g_xh[N_TOK * DIM];
__device__ __align__(16) __nv_bfloat16 g_xl[N_TOK * DIM];
__device__ __align__(16) __nv_bfloat16 g_wh[NEXP * DIM * DIM];
__device__ __align__(16) __nv_bfloat16 g_wl[NEXP * DIM * DIM];
__device__ int   g_routes[N_TOK];
__device__ float g_probs[N_TOK];
__device__ int   g_blkcnt[NEXP * NBLK];
__device__ int   g_blkoff[NEXP * NBLK];
__device__ int   g_idx[NEXP * CAP];
__device__ int   g_count[NEXP];
__device__ int   g_scanflag;

// ---------------- PTX helpers ----------------------------------------------
__device__ __forceinline__ uint32_t smem_u32(const void* p) {
    uint32_t a;
    asm("{ .reg .u64 t; cvta.to.shared.u64 t, %1; cvt.u32.u64 %0, t; }"
        : "=r"(a) : "l"(p));
    return a;
}
__device__ __forceinline__ uint32_t swz(uint32_t b) {   // 64B-row swizzle
    return b ^ ((b >> 3) & 0x30);
}
__device__ __forceinline__ void cp16(uint32_t dst, const void* src) {
    asm volatile("cp.async.cg.shared.global [%0], [%1], 16;\n"
                 :: "r"(dst), "l"(src));
}
#define CP_COMMIT() asm volatile("cp.async.commit_group;\n" ::: "memory")
#define CP_WAIT1()  asm volatile("cp.async.wait_group 1;\n" ::: "memory")

__device__ __forceinline__ void ldsm4(uint32_t* r, uint32_t a) {
    asm volatile("ldmatrix.sync.aligned.m8n8.x4.shared.b16 {%0,%1,%2,%3}, [%4];\n"
                 : "=r"(r[0]), "=r"(r[1]), "=r"(r[2]), "=r"(r[3]) : "r"(a));
}
__device__ __forceinline__ void mma16816(float* d, const uint32_t* a,
                                         const uint32_t* b) {
    asm volatile(
        "mma.sync.aligned.m16n8k16.row.col.f32.bf16.bf16.f32 "
        "{%0,%1,%2,%3}, {%4,%5,%6,%7}, {%8,%9}, {%0,%1,%2,%3};\n"
        : "+f"(d[0]), "+f"(d[1]), "+f"(d[2]), "+f"(d[3])
        : "r"(a[0]), "r"(a[1]), "r"(a[2]), "r"(a[3]), "r"(b[0]), "r"(b[1]));
}

// split one float4 into hi/lo bf16x4 packed as uint2
__device__ __forceinline__ void split4(float4 v, uint2& hv, uint2& lv) {
    float hx = __bfloat162float(__float2bfloat16_rn(v.x));
    float hy = __bfloat162float(__float2bfloat16_rn(v.y));
    float hz = __bfloat162float(__float2bfloat16_rn(v.z));
    float hw = __bfloat162float(__float2bfloat16_rn(v.w));
    __nv_bfloat162 h0 = __floats2bfloat162_rn(hx, hy);
    __nv_bfloat162 h1 = __floats2bfloat162_rn(hz, hw);
    __nv_bfloat162 l0 = __floats2bfloat162_rn(v.x - hx, v.y - hy);
    __nv_bfloat162 l1 = __floats2bfloat162_rn(v.z - hz, v.w - hw);
    hv = make_uint2(*(uint32_t*)&h0, *(uint32_t*)&h1);
    lv = make_uint2(*(uint32_t*)&l0, *(uint32_t*)&l1);
}

// split one float2 into hi/lo bf16x2 packed as uint32
__device__ __forceinline__ void split2(float2 v, uint32_t& hv, uint32_t& lv) {
    float hx = __bfloat162float(__float2bfloat16_rn(v.x));
    float hy = __bfloat162float(__float2bfloat16_rn(v.y));
    __nv_bfloat162 h = __floats2bfloat162_rn(hx, hy);
    __nv_bfloat162 l = __floats2bfloat162_rn(v.x - hx, v.y - hy);
    hv = *(uint32_t*)&h;
    lv = *(uint32_t*)&l;
}

// ---------------- 1) fused router + x-split + W-split + block counts --------
// Router: float2 (k-pair) loads + uint32 hi/lo stores, two passes of 8
// experts (acc[4][8]); whole kernel reg-capped at 64 via launch_bounds(256,4).
#define RW_ROUTER_BLOCKS NBLK                               // 1024
#define RW_WCONV_BLOCKS  (NEXP * DIM * DIM / 4 / 256)       // 4096

__global__ void __launch_bounds__(256, 4)
rw_kernel(const float* __restrict__ x,
          const float* __restrict__ sw,
          const float* __restrict__ sb,
          const float* __restrict__ ew) {
    int tid = threadIdx.x;

    if (blockIdx.x >= RW_ROUTER_BLOCKS) {
        // ---- wconv part (streaming, float4 in / uint2 x2 out) ----
        size_t idx = (size_t)(blockIdx.x - RW_ROUTER_BLOCKS) * 256 + tid;
        float4 v = ((const float4*)ew)[idx];
        uint2 hv, lv;
        split4(v, hv, lv);
        *(uint2*)(g_wh + idx * 4) = hv;
        *(uint2*)(g_wl + idx * 4) = lv;
        return;
    }

    // ---- router part: 32 tokens/block, 4 tokens/warp, float2 k-pairs ----
    if (blockIdx.x == 0 && tid == 0) g_scanflag = 0;   // reset sf flag barrier
    __shared__ float s_w[NEXP][DIM];
    __shared__ float s_b[NEXP];
    __shared__ float s_log[32][NEXP];
    __shared__ int   s_routes[32];
    for (int i = tid; i < NEXP * DIM / 4; i += 256)
        ((float4*)&s_w[0][0])[i] = ((const float4*)sw)[i];
    if (tid < NEXP) s_b[tid] = sb[tid];
    __syncthreads();

    int warp = tid >> 5, lane = tid & 31;
    int t0 = blockIdx.x * 32 + warp * 4;

#pragma unroll 1
    for (int half = 0; half < 2; half++) {
        float acc[4][8];
#pragma unroll
        for (int tt = 0; tt < 4; tt++)
#pragma unroll
            for (int e = 0; e < 8; e++) acc[tt][e] = 0.f;

#pragma unroll
        for (int j = 0; j < DIM / 64; j++) {   // 8 iters, float2 index
            int f2 = j * 32 + lane;
            float2 xv[4];
#pragma unroll
            for (int tt = 0; tt < 4; tt++) {
                xv[tt] = ((const float2*)(x + (size_t)(t0 + tt) * DIM))[f2];
                if (half == 0) {
                    uint32_t hv, lv;
                    split2(xv[tt], hv, lv);
                    *(uint32_t*)(g_xh + (size_t)(t0 + tt) * DIM + f2 * 2) = hv;
                    *(uint32_t*)(g_xl + (size_t)(t0 + tt) * DIM + f2 * 2) = lv;
                }
            }
#pragma unroll
            for (int e = 0; e < 8; e++) {
                float2 w = ((const float2*)&s_w[half * 8 + e][0])[f2];
#pragma unroll
                for (int tt = 0; tt < 4; tt++) {
                    acc[tt][e] = fmaf(xv[tt].x, w.x, acc[tt][e]);
                    acc[tt][e] = fmaf(xv[tt].y, w.y, acc[tt][e]);
                }
            }
        }
#pragma unroll
        for (int tt = 0; tt < 4; tt++)
#pragma unroll
            for (int e = 0; e < 8; e++)
#pragma unroll
                for (int off = 16; off > 0; off >>= 1)
                    acc[tt][e] += __shfl_xor_sync(0xffffffffu, acc[tt][e], off);
        if (lane == 0) {
#pragma unroll
            for (int tt = 0; tt < 4; tt++)
#pragma unroll
                for (int e = 0; e < 8; e++)
                    s_log[warp * 4 + tt][half * 8 + e] = acc[tt][e];
        }
    }
    __syncwarp();

    if (lane < 4) {
        int tt = lane;
        float lmax = -1e30f; int am = 0;
        float l[NEXP];
#pragma unroll
        for (int e = 0; e < NEXP; e++) {
            l[e] = s_log[warp * 4 + tt][e] + s_b[e];
            if (l[e] > lmax) { lmax = l[e]; am = e; }
        }
        float sum = 0.f;
#pragma unroll
        for (int e = 0; e < NEXP; e++) sum += expf(l[e] - lmax);
        g_routes[t0 + tt] = am;
        g_probs[t0 + tt]  = 1.f / sum;
        s_routes[warp * 4 + tt] = am;
    }
    __syncthreads();
    if (tid < NEXP) {
        int c = 0;
#pragma unroll
        for (int i = 0; i < 32; i++) c += (s_routes[i] == tid);
        g_blkcnt[tid * NBLK + blockIdx.x] = c;
    }
}

// ---------------- 2) merged scan + finalize ----------------------------------
__global__ void __launch_bounds__(256, 8)
sf_kernel(const float* __restrict__ x, float* __restrict__ out) {
    __shared__ int s_ws[8];
    __shared__ unsigned s_drop;
    int blk = blockIdx.x;
    int tid = threadIdx.x, lane = tid & 31, wid = tid >> 5;

    if (blk < NEXP) {
        int e = blk;
        int4 c = ((const int4*)(g_blkcnt + e * NBLK))[tid];
        int sum = c.x + c.y + c.z + c.w;
        int inc = sum;
#pragma unroll
        for (int off = 1; off < 32; off <<= 1) {
            int o = __shfl_up_sync(0xffffffffu, inc, off);
            if (lane >= off) inc += o;
        }
        if (lane == 31) s_ws[wid] = inc;
        __syncthreads();
        if (wid == 0 && lane < 8) {
            int v = s_ws[lane];
            int wi = v;
#pragma unroll
            for (int off = 1; off < 8; off <<= 1) {
                int o = __shfl_up_sync(0xffu, wi, off);
                if (lane >= off) wi += o;
            }
            s_ws[lane] = wi - v;
        }
        __syncthreads();
        int excl = s_ws[wid] + inc - sum;
        int4 o;
        o.x = excl; o.y = excl + c.x; o.z = o.y + c.y; o.w = o.z + c.z;
        ((int4*)(g_blkoff + e * NBLK))[tid] = o;
        if (tid == 255) {
            int tot = excl + sum;
            g_count[e] = tot < CAP ? tot : CAP;
        }
        __syncthreads();
        if (tid == 0) {
            __threadfence();
            atomicAdd(&g_scanflag, 1);
        }
    }

    if (tid == 0) {
        while (*(volatile int*)&g_scanflag < NEXP) { }
        s_drop = 0;
    }
    __syncthreads();
    __threadfence();

    if (tid < 32) {
        int t = blk * 32 + tid;
        int r = g_routes[t];
        unsigned mask = __match_any_sync(0xffffffffu, r);
        int rank = __popc(mask & ((1u << tid) - 1u));
        int pos = g_blkoff[r * NBLK + blk] + rank;
        bool keep = pos < CAP;
        if (keep) g_idx[r * CAP + pos] = t;
        unsigned dm = __ballot_sync(0xffffffffu, !keep);
        if (tid == 0) s_drop = dm;
    }
    __syncthreads();
    unsigned dm = s_drop;
    while (dm) {
        int d = __ffs(dm) - 1;
        dm &= dm - 1;
        int t = blk * 32 + d;
        float p = g_probs[t];
        if (tid < 128) {
            float4 v = ((const float4*)(x + (size_t)t * DIM))[tid];
            v.x *= p; v.y *= p; v.z *= p; v.w *= p;
            ((float4*)(out + (size_t)t * DIM))[tid] = v;
        }
    }
}

// ---------------- 3) mma.sync grouped gather-GEMM (R10, FROZEN) -------------
#define BM 128
#define BN 128
#define BK 32
#define NSTG 3
#define OFF_AH 0
#define OFF_AL (8 * 1024)
#define OFF_BH (16 * 1024)
#define OFF_BL (24 * 1024)
#define STG_BYTES (32 * 1024)
#define SMEM_DYN  (NSTG * STG_BYTES + 1024)

__global__ void __launch_bounds__(256, 2)
moe_mma_kernel(const float* __restrict__ eb, float* __restrict__ out) {
    extern __shared__ char dynsmem[];
    __shared__ int   s_idx[BM];
    __shared__ float s_prob[BM];
    __shared__ float s_bias[BN];

    int e = blockIdx.z;
    int cnt = g_count[e];
    int m0 = blockIdx.x * BM;
    if (m0 >= cnt) return;
    int n0 = blockIdx.y * BN;
    int tid = threadIdx.x, wid = tid >> 5, lane = tid & 31;
    int wm = wid >> 2, wn = wid & 3;

    char* sbase = dynsmem + ((1024u - (smem_u32(dynsmem) & 1023u)) & 1023u);
    uint32_t u0 = smem_u32(sbase);

    if (tid < BM) {
        int m = m0 + tid;
        int t = g_idx[e * CAP + (m < cnt ? m : cnt - 1)];
        s_idx[tid] = t;
        s_prob[tid] = g_probs[t];
    }
    if (tid < BN) s_bias[tid] = eb[e * DIM + n0 + tid];
    __syncthreads();

    const __nv_bfloat16 *srcAh[2], *srcAl[2], *srcBh[2], *srcBl[2];
    uint32_t a_dst[2], b_dst[2];
#pragma unroll
    for (int i = 0; i < 2; i++) {
        int idx = tid + 256 * i;
        int row = idx >> 2, ch = idx & 3;
        size_t ao = (size_t)s_idx[row] * DIM + ch * 8;
        srcAh[i] = g_xh + ao;
        srcAl[i] = g_xl + ao;
        size_t bo = (size_t)(e * DIM + n0 + row) * DIM + ch * 8;
        srcBh[i] = g_wh + bo;
        srcBl[i] = g_wl + bo;
        a_dst[i] = swz((uint32_t)(row * 64 + ch * 16));
        b_dst[i] = a_dst[i];
    }

    const int KT = DIM / BK;   // 16
#pragma unroll
    for (int pre = 0; pre < 2; pre++) {
        uint32_t sb = u0 + pre * STG_BYTES;
        int kb = pre * BK;
#pragma unroll
        for (int i = 0; i < 2; i++) {
            cp16(sb + OFF_AH + a_dst[i], srcAh[i] + kb);
            cp16(sb + OFF_AL + a_dst[i], srcAl[i] + kb);
            cp16(sb + OFF_BH + b_dst[i], srcBh[i] + kb);
            cp16(sb + OFF_BL + b_dst[i], srcBl[i] + kb);
        }
        CP_COMMIT();
    }

    float acc[4][4][4];
#pragma unroll
    for (int mi = 0; mi < 4; mi++)
#pragma unroll
        for (int nj = 0; nj < 4; nj++)
#pragma unroll
            for (int k = 0; k < 4; k++) acc[mi][nj][k] = 0.f;

#pragma unroll 1
    for (int kt = 0; kt < KT; kt++) {
        CP_WAIT1();
        __syncthreads();
        if (kt + 2 < KT) {
            uint32_t sb = u0 + ((kt + 2) % NSTG) * STG_BYTES;
            int kb = (kt + 2) * BK;
#pragma unroll
            for (int i = 0; i < 2; i++) {
                cp16(sb + OFF_AH + a_dst[i], srcAh[i] + kb);
                cp16(sb + OFF_AL + a_dst[i], srcAl[i] + kb);
                cp16(sb + OFF_BH + b_dst[i], srcBh[i] + kb);
                cp16(sb + OFF_BL + b_dst[i], srcBl[i] + kb);
            }
        }
        CP_COMMIT();

        uint32_t sb = u0 + (kt % NSTG) * STG_BYTES;
#pragma unroll
        for (int ks = 0; ks < 2; ks++) {
            uint32_t ah[4][4], al[4][4], bh[4][2], bl[4][2];
            uint32_t a_addr[4], b_addr[2];
#pragma unroll
            for (int mi = 0; mi < 4; mi++) {
                uint32_t off = (uint32_t)((wm * 64 + mi * 16 + (lane & 15)) * 64 +
                                          ks * 32 + (lane >> 4) * 16);
                a_addr[mi] = sb + swz(off);
            }
#pragma unroll
            for (int nj2 = 0; nj2 < 2; nj2++) {
                uint32_t off = (uint32_t)((wn * 32 + nj2 * 16 +
                                           ((lane >> 4) & 1) * 8 + (lane & 7)) * 64 +
                                          ks * 32 + ((lane >> 3) & 1) * 16);
                b_addr[nj2] = sb + swz(off);
            }

            // wave 1: B-hi + A-hi, then ah*bh
#pragma unroll
            for (int nj2 = 0; nj2 < 2; nj2++) {
                uint32_t r[4];
                ldsm4(r, b_addr[nj2] + OFF_BH);
                bh[nj2 * 2][0] = r[0]; bh[nj2 * 2][1] = r[1];
                bh[nj2 * 2 + 1][0] = r[2]; bh[nj2 * 2 + 1][1] = r[3];
            }
#pragma unroll
            for (int mi = 0; mi < 4; mi++)
                ldsm4(ah[mi], a_addr[mi] + OFF_AH);
#pragma unroll
            for (int mi = 0; mi < 4; mi++)
#pragma unroll
                for (int nj = 0; nj < 4; nj++)
                    mma16816(acc[mi][nj], ah[mi], bh[nj]);

            // wave 2: B-lo, then ah*bl
#pragma unroll
            for (int nj2 = 0; nj2 < 2; nj2++) {
                uint32_t r[4];
                ldsm4(r, b_addr[nj2] + OFF_BL);
                bl[nj2 * 2][0] = r[0]; bl[nj2 * 2][1] = r[1];
                bl[nj2 * 2 + 1][0] = r[2]; bl[nj2 * 2 + 1][1] = r[3];
            }
#pragma unroll
            for (int mi = 0; mi < 4; mi++)
#pragma unroll
                for (int nj = 0; nj < 4; nj++)
                    mma16816(acc[mi][nj], ah[mi], bl[nj]);

            // wave 3: A-lo, then al*bh
#pragma unroll
            for (int mi = 0; mi < 4; mi++)
                ldsm4(al[mi], a_addr[mi] + OFF_AL);
#pragma unroll
            for (int mi = 0; mi < 4; mi++)
#pragma unroll
                for (int nj = 0; nj < 4; nj++)
                    mma16816(acc[mi][nj], al[mi], bh[nj]);
        }
    }

    // epilogue: +bias, *prob, scatter rows to out
#pragma unroll
    for (int mi = 0; mi < 4; mi++) {
        int r0 = wm * 64 + mi * 16 + (lane >> 2);
        int r1 = r0 + 8;
        bool ok0 = (m0 + r0) < cnt;
        bool ok1 = (m0 + r1) < cnt;
        float p0 = s_prob[r0], p1 = s_prob[r1];
        float* o0 = out + (size_t)s_idx[r0] * DIM + n0;
        float* o1 = out + (size_t)s_idx[r1] * DIM + n0;
#pragma unroll
        for (int nj = 0; nj < 4; nj++) {
            int col = wn * 32 + nj * 8 + 2 * (lane & 3);
            float b0 = s_bias[col], b1 = s_bias[col + 1];
            if (ok0) {
                float2 v = make_float2((acc[mi][nj][0] + b0) * p0,
                                       (acc[mi][nj][1] + b1) * p0);
                *(float2*)(o0 + col) = v;
            }
            if (ok1) {
                float2 v = make_float2((acc[mi][nj][2] + b0) * p1,
                                       (acc[mi][nj][3] + b1) * p1);
                *(float2*)(o1 + col) = v;
            }
        }
    }
}

// ---------------------------------------------------------------------------
extern "C" void kernel_launch(void* const* d_in, const int* in_sizes, int n_in,
                              void* d_out, int out_size) {
    const float* x   = (const float*)d_in[0];   // [N, D]
    const float* sw  = (const float*)d_in[1];   // [E, D]
    const float* sb  = (const float*)d_in[2];   // [E]
    const float* ew  = (const float*)d_in[3];   // [E, D, D]
    const float* ebv = (const float*)d_in[4];   // [E, D]
    float* out = (float*)d_out;

    cudaFuncSetAttribute(moe_mma_kernel,
                         cudaFuncAttributeMaxDynamicSharedMemorySize, SMEM_DYN);

    rw_kernel<<<RW_ROUTER_BLOCKS + RW_WCONV_BLOCKS, 256>>>(x, sw, sb, ew);
    sf_kernel<<<NBLK, 256>>>(x, out);

    dim3 grid((CAP + BM - 1) / BM, DIM / BN, NEXP);
    moe_mma_kernel<<<grid, 256, SMEM_DYN>>>(ebv, out);
}